// round 9
// baseline (speedup 1.0000x reference)
#include <cuda_runtime.h>
#include <math.h>

#define NS    2048
#define D     512
#define D4    128
#define DPAD  129          // padded float4 row stride in stage (kills bank conflicts)
#define LYR   8
#define NT    7            // layer pairs
#define NCLS  128
#define MAXN  64
#define SCAP  13           // staged rows: 13*129*16B=26.8KB -> 7 CTAs/SM, single wave
#define KTOP  5

// ---------------- device scratch (no allocations allowed) ----------------
__device__ int           g_smap[NCLS * MAXN];    // subset member-position map
__device__ int           g_n[NCLS];
__device__ int           g_n2[NCLS];
__device__ float         g_sim[(size_t)LYR * NCLS * MAXN * MAXN];   // full-class sims
__device__ float         g_A[(size_t)LYR * NCLS * MAXN * MAXN];     // masked symmetric A
__device__ unsigned char g_msk[(size_t)LYR * NCLS * MAXN * MAXN];   // symmetric masks
__device__ float         g_ema[LYR * NCLS * MAXN];
__device__ float         g_pnum[NT * NCLS];
__device__ float         g_pden[NT * NCLS];
__device__ int           g_ctr = 0;

// ---------------- kernel 1: per (layer,class) full-class cosine blocks -------------
__global__ __launch_bounds__(256, 7) void sims_kernel(const float* __restrict__ feats,
                                                      const int*   __restrict__ labels,
                                                      const int*   __restrict__ sids32) {
    extern __shared__ float4 stage[];            // SCAP rows, DPAD float4 stride
    __shared__ int           midx[MAXN];
    __shared__ float         sinv[MAXN];
    __shared__ const float4* rowp[MAXN];
    __shared__ int           scan[256];
    __shared__ int           sn;

    const int cls = blockIdx.x & (NCLS - 1);
    const int l   = blockIdx.x >> 7;
    const int tid = threadIdx.x;
    // sample_ids = arange. int64 -> int32 words [0,0,1,0,...]; word[2]==1 iff int64
    const int is64 = (sids32[2] == 1) ? 1 : 0;

    // ---- member list (each CTA derives it independently; labels are L2-hot) ----
    int loc[8]; int c = 0;
#pragma unroll
    for (int k = 0; k < 8; k++) {
        int gi = tid * 8 + k;
        int lb = is64 ? labels[2 * gi] : labels[gi];
        if (lb == cls) loc[c++] = gi;
    }
    scan[tid] = c;
    __syncthreads();
    for (int off = 1; off < 256; off <<= 1) {
        int v = (tid >= off) ? scan[tid - off] : 0;
        __syncthreads();
        scan[tid] += v;
        __syncthreads();
    }
    int start = scan[tid] - c;
    for (int k = 0; k < c; k++) {
        int pos = start + k;
        if (pos < MAXN) midx[pos] = loc[k];
    }
    if (tid == 255) sn = scan[255] < MAXN ? scan[255] : MAXN;
    __syncthreads();
    const int n = sn;
    if (l == 0 && tid == 0) g_n[cls] = n;
    if (n == 0) return;

    // ---- stage rows (padded); rows beyond SCAP fall back to global (L1-resident) ----
    const float* F = feats + (size_t)l * NS * D;
    int nst = n < SCAP ? n : SCAP;
    for (int q = tid; q < nst * D4; q += 256) {
        int r = q >> 7, cc = q & 127;
        stage[r * DPAD + cc] = ((const float4*)(F + (size_t)midx[r] * D))[cc];
    }
    for (int r = tid; r < n; r += 256)
        rowp[r] = (r < nst) ? (const float4*)(stage + r * DPAD)
                            : (const float4*)(F + (size_t)midx[r] * D);
    __syncthreads();

    // ---- inverse norms (warp per row; same reduction tree as reference path) ----
    {
        const int w = tid >> 5, lane = tid & 31;
        for (int r = w; r < n; r += 8) {
            const float4* a = rowp[r];
            float ss = 0.f;
#pragma unroll
            for (int k = 0; k < 4; k++) {
                float4 v = a[lane + 32 * k];
                ss += v.x * v.x + v.y * v.y + v.z * v.z + v.w * v.w;
            }
#pragma unroll
            for (int o = 16; o; o >>= 1) ss += __shfl_xor_sync(0xffffffffu, ss, o);
            if (lane == 0) sinv[r] = 1.0f / fmaxf(sqrtf(ss), 1e-8f);
        }
    }
    __syncthreads();

    // ---- sims: 4 pairs per warp (8 lanes per dot), write straight to global ----
    float* gsim = g_sim + (size_t)(l * NCLS + cls) * MAXN * MAXN;
    {
        const int w = tid >> 5, lane = tid & 31;
        const int grp = lane >> 3, l8 = lane & 7;
        const int npair = n * (n - 1) / 2;
        for (int pb = w * 4; pb < npair; pb += 32) {
            int p  = pb + grp;
            int pc = (p < npair) ? p : npair - 1;
            int i = (int)((1.0f + sqrtf(8.0f * (float)pc + 1.0f)) * 0.5f);
            while (i * (i - 1) / 2 > pc) i--;
            while ((i + 1) * i / 2 <= pc) i++;
            int j = pc - i * (i - 1) / 2;
            const float4* a = rowp[i];
            const float4* b = rowp[j];
            float dot = 0.f;
#pragma unroll
            for (int k = 0; k < 16; k++) {
                float4 x = a[l8 + 8 * k];
                float4 y = b[l8 + 8 * k];
                dot += x.x * y.x + x.y * y.y + x.z * y.z + x.w * y.w;
            }
#pragma unroll
            for (int o = 4; o; o >>= 1) dot += __shfl_xor_sync(0xffffffffu, dot, o);
            if (l8 == 0 && p < npair) {
                float s = dot * sinv[i] * sinv[j];
                s = fminf(fmaxf(s, -1.0f), 1.0f);   // fp32 clip bounds round to +/-1
                gsim[i * MAXN + j] = s;
                gsim[j * MAXN + i] = s;
            }
        }
        // diag = clip(~1, 1-1e-8) -> exactly 1.0f in fp32
        for (int i = tid; i < n; i += 256) gsim[i * MAXN + i] = 1.0f;
    }
}

// top-5 with jax.lax.top_k tie-break (equal values -> lower index)
__device__ __forceinline__ void top5_row(const float* row, int n, int self, int* ch) {
#pragma unroll
    for (int t = 0; t < KTOP; t++) {
        float bv = 0.f;   // only strictly-positive sims are candidates
        int   bj = -1;
        for (int j = 0; j < n; j++) {
            if (j == self) continue;
            bool used = false;
            for (int u = 0; u < t; u++) if (ch[u] == j) used = true;
            if (used) continue;
            float v = row[j];
            if (v > bv) { bv = v; bj = j; }
        }
        ch[t] = bj;
    }
}

// knn mask + ema on an n2 x n2 sim block; writes compacted masked-A, sym-mask, ema
__device__ __forceinline__ void knn_store(const float* sim, int n2, int l, int cls,
                                          unsigned char* msk, unsigned char* keep) {
    const int tid = threadIdx.x;
    for (int p = tid; p < n2 * MAXN; p += blockDim.x) msk[p] = 0;
    __syncthreads();
    float emaval = 0.f;
    if (tid < n2) {
        const float* row = sim + tid * MAXN;
        float rs = 0.f;
        int dg = 0, cand = 0;
        for (int j = 0; j < n2; j++) {
            float v = row[j];
            if (v > 0.f) { rs += v; dg++; if (j != tid) cand++; }
        }
        float degf = (float)(dg > 0 ? dg : 1);
        float sc   = 1.0f / (1.0f + expf(-rs / degf));
        emaval    = 0.45f + 0.1f * sc;           // MOM*0.5 + (1-MOM)*score
        keep[tid] = (cand >= KTOP) ? 1 : 0;
    }
    __syncthreads();
    if (tid < n2 && keep[tid]) {
        const float* row = sim + tid * MAXN;
        int ch[KTOP];
        top5_row(row, n2, tid, ch);
#pragma unroll
        for (int t = 0; t < KTOP; t++) {
            int j = ch[t];
            if (j >= 0 && keep[j]) msk[tid * MAXN + j] = 1;
        }
    }
    __syncthreads();
    float*         gA = g_A   + (size_t)(l * NCLS + cls) * MAXN * MAXN;
    unsigned char* gm = g_msk + (size_t)(l * NCLS + cls) * MAXN * MAXN;
    for (int p = tid; p < n2 * MAXN; p += blockDim.x) {
        int i = p >> 6, j = p & 63;
        unsigned char sym = (unsigned char)(msk[p] | ((j < n2) ? msk[j * MAXN + i] : 0));
        gm[p] = sym;
        gA[p] = sym ? sim[p] : 0.f;              // A = sim * M (masked sims > 0)
    }
    if (tid < n2) g_ema[(l * NCLS + cls) * MAXN + tid] = emaval;
}

// ---------------- kernel 2: subset selection + layer-7 compacted outputs -----------
__global__ __launch_bounds__(256) void subset_kernel() {
    __shared__ float         sim[MAXN * MAXN];
    __shared__ float         sim2[MAXN * MAXN];
    __shared__ unsigned char msk[MAXN * MAXN];
    __shared__ unsigned char keep[MAXN], insub[MAXN];
    __shared__ int           smap[MAXN];
    __shared__ int           sn2;

    const int cls = blockIdx.x, tid = threadIdx.x;
    const int n = g_n[cls];
    if (n == 0) { if (tid == 0) g_n2[cls] = 0; return; }

    const float* gsim = g_sim + (size_t)((LYR - 1) * NCLS + cls) * MAXN * MAXN;
    for (int p = tid; p < n * MAXN; p += 256) sim[p] = gsim[p];
    __syncthreads();

    if (tid < n) {
        insub[tid] = 0;
        const float* row = sim + tid * MAXN;
        int cand = 0;
        for (int j = 0; j < n; j++)
            if (j != tid && row[j] > 0.f) cand++;
        keep[tid] = (cand >= KTOP) ? 1 : 0;
    }
    __syncthreads();
    if (tid < n && keep[tid]) {
        const float* row = sim + tid * MAXN;
        int ch[KTOP];
        top5_row(row, n, tid, ch);
#pragma unroll
        for (int t = 0; t < KTOP; t++) {
            int j = ch[t];
            if (j >= 0 && keep[j]) { insub[tid] = 1; insub[j] = 1; }  // benign race
        }
    }
    __syncthreads();
    if (tid == 0) {
        int m = 0;
        for (int i = 0; i < n; i++)
            if (insub[i]) { smap[m] = i; g_smap[cls * MAXN + m] = i; m++; }
        sn2 = m;
        g_n2[cls] = m;
    }
    __syncthreads();
    const int n2 = sn2;
    if (n2 == 0) return;

    // layer-7 compacted outputs straight from the in-smem full-class block
    for (int p = tid; p < n2 * n2; p += 256) {
        int i = p / n2, j = p % n2;
        sim2[i * MAXN + j] = sim[smap[i] * MAXN + smap[j]];
    }
    __syncthreads();
    knn_store(sim2, n2, LYR - 1, cls, msk, keep);
}

// ---------------- kernel 3: per (class, layer 0..6) subset knn from stored sims ----
__global__ __launch_bounds__(256) void knn_kernel() {
    __shared__ int           smap[MAXN];
    __shared__ float         sim[MAXN * MAXN];
    __shared__ unsigned char msk[MAXN * MAXN];
    __shared__ unsigned char keep[MAXN];

    const int cls = blockIdx.x & (NCLS - 1);
    const int l   = blockIdx.x >> 7;        // 0..6
    const int tid = threadIdx.x;
    const int n2  = g_n2[cls];
    if (n2 == 0) return;

    for (int r = tid; r < n2; r += 256) smap[r] = g_smap[cls * MAXN + r];
    __syncthreads();
    const float* gsim = g_sim + (size_t)(l * NCLS + cls) * MAXN * MAXN;
    for (int p = tid; p < n2 * n2; p += 256) {
        int i = p / n2, j = p % n2;
        sim[i * MAXN + j] = gsim[smap[i] * MAXN + smap[j]];
    }
    __syncthreads();
    knn_store(sim, n2, l, cls, msk, keep);
}

// ---------------- kernel 4: one block per class streams all 7 layer pairs ----------
__global__ __launch_bounds__(256) void accum_final(float* __restrict__ out) {
    __shared__ float esh[LYR][MAXN];
    __shared__ float swn[8], swd[8];
    __shared__ int   done;

    const int cls = blockIdx.x;              // 0..127
    const int tid = threadIdx.x;
    const int n2  = g_n2[cls];

    if (n2 > 1) {
        for (int q = tid; q < LYR * MAXN; q += 256) {
            int l = q >> 6, r = q & 63;
            esh[l][r] = (r < n2) ? g_ema[(l * NCLS + cls) * MAXN + r] : 0.f;
        }
        __syncthreads();
        for (int t = 0; t < NT; t++) {
            const size_t bp = (size_t)(t * NCLS + cls) * MAXN * MAXN;
            const size_t bc = (size_t)((t + 1) * NCLS + cls) * MAXN * MAXN;
            float pnum = 0.f, pden = 0.f;
            // contiguous streaming; zero masks on diagonal & tail auto-skip
            for (int p = tid; p < n2 * MAXN; p += 256) {
                int ml = g_msk[bp + p];
                int mc = g_msk[bc + p];
                if (ml | mc) {
                    int i = p >> 6, j = p & 63;
                    float w = esh[t][i] * esh[t][j];
                    float d = g_A[bc + p] - g_A[bp + p];
                    pnum += d * d * w;
                    pden += w;
                }
            }
#pragma unroll
            for (int o = 16; o; o >>= 1) {
                pnum += __shfl_xor_sync(0xffffffffu, pnum, o);
                pden += __shfl_xor_sync(0xffffffffu, pden, o);
            }
            if ((tid & 31) == 0) { swn[tid >> 5] = pnum; swd[tid >> 5] = pden; }
            __syncthreads();
            if (tid == 0) {
                float tn = 0.f, td = 0.f;
                for (int q = 0; q < 8; q++) { tn += swn[q]; td += swd[q]; }
                g_pnum[t * NCLS + cls] = tn;
                g_pden[t * NCLS + cls] = td;
            }
            __syncthreads();
        }
    } else if (tid < NT) {
        g_pnum[tid * NCLS + cls] = 0.f;
        g_pden[tid * NCLS + cls] = 0.f;
    }
    __threadfence();
    __syncthreads();
    if (tid == 0) {
        int old = atomicAdd(&g_ctr, 1);
        done = (old == NCLS - 1) ? 1 : 0;
    }
    __syncthreads();
    if (!done) return;

    // last block: deterministic combine of all 7*128 partials
    __shared__ float red[128];
    __shared__ float tnum[NT], tden[NT];
    for (int t2 = 0; t2 < NT; t2++) {
        if (tid < 128) red[tid] = g_pnum[t2 * NCLS + tid];
        __syncthreads();
        for (int s = 64; s; s >>= 1) { if (tid < s) red[tid] += red[tid + s]; __syncthreads(); }
        if (tid == 0) tnum[t2] = red[0];
        __syncthreads();
        if (tid < 128) red[tid] = g_pden[t2 * NCLS + tid];
        __syncthreads();
        for (int s = 64; s; s >>= 1) { if (tid < s) red[tid] += red[tid + s]; __syncthreads(); }
        if (tid == 0) tden[t2] = red[0];
        __syncthreads();
    }
    if (tid == 0) {
        float raw = 0.f;
        for (int t2 = 0; t2 < NT; t2++)
            if (tden[t2] > 0.f)                       // M_eff.sum() > 0 <=> any edge
                raw += tnum[t2] / fmaxf(tden[t2], 1e-8f);
        out[0] = 16.0f * (raw / 7.0f);                // LAMBDA_ALIGN_K * raw / (L-1)
        g_ctr = 0;                                    // reset for next graph replay
    }
}

extern "C" void kernel_launch(void* const* d_in, const int* in_sizes, int n_in,
                              void* d_out, int out_size) {
    const float* feats  = (const float*)d_in[0];
    const int*   labels = (const int*)d_in[1];   // int32 or int64; detected at runtime
    const int*   sids   = (const int*)d_in[2];
    float*       out    = (float*)d_out;

    const int DYN = SCAP * DPAD * 16;            // 26.8 KB padded stage
    cudaFuncSetAttribute(sims_kernel, cudaFuncAttributeMaxDynamicSharedMemorySize, DYN);

    sims_kernel<<<LYR * NCLS, 256, DYN>>>(feats, labels, sids);
    subset_kernel<<<NCLS, 256>>>();
    knn_kernel<<<NT * NCLS, 256>>>();
    accum_final<<<NCLS, 256>>>(out);
}

// round 10
// speedup vs baseline: 1.1779x; 1.1779x over previous
#include <cuda_runtime.h>
#include <math.h>
#include <stdint.h>

#define NS    2048
#define D     512
#define D4    128
#define DPAD  129          // padded float4 row stride in stage (kills bank conflicts)
#define LYR   8
#define NT    7            // layer pairs
#define NCLS  128
#define MAXN  64
#define SCAP  20           // staged rows: 20*129*16B = 41.3KB -> 5 CTAs/SM
#define KTOP  5

// ---------------- device scratch (no allocations allowed) ----------------
__device__ int           g_mem[NCLS * MAXN];     // full-class member lists
__device__ int           g_n[NCLS];
__device__ int           g_smap[NCLS * MAXN];    // subset member-position map
__device__ int           g_n2[NCLS];
__device__ float         g_sim[(size_t)LYR * NCLS * MAXN * MAXN];   // full-class sims
__device__ float         g_A[(size_t)LYR * NCLS * MAXN * MAXN];     // masked symmetric A
__device__ unsigned char g_msk[(size_t)LYR * NCLS * MAXN * MAXN];   // symmetric masks
__device__ float         g_ema[LYR * NCLS * MAXN];
__device__ float         g_pnum[NT * NCLS];
__device__ float         g_pden[NT * NCLS];
__device__ int           g_ctr = 0;

__device__ __forceinline__ void cp_async16(uint32_t smem_addr, const void* gptr) {
    asm volatile("cp.async.cg.shared.global [%0], [%1], 16;\n"
                 :: "r"(smem_addr), "l"(gptr) : "memory");
}

// ---------------- kernel 0: member lists (hoisted out of the heavy kernel) ---------
__global__ __launch_bounds__(256) void members_kernel(const int* __restrict__ labels,
                                                      const int* __restrict__ sids32) {
    __shared__ int scan[256];
    const int cls = blockIdx.x, tid = threadIdx.x;
    // sample_ids = arange. int64 -> int32 words [0,0,1,0,...]; word[2]==1 iff int64
    const int is64 = (sids32[2] == 1) ? 1 : 0;

    int loc[8]; int c = 0;
#pragma unroll
    for (int k = 0; k < 8; k++) {
        int gi = tid * 8 + k;
        int lb = is64 ? labels[2 * gi] : labels[gi];
        if (lb == cls) loc[c++] = gi;
    }
    scan[tid] = c;
    __syncthreads();
    for (int off = 1; off < 256; off <<= 1) {
        int v = (tid >= off) ? scan[tid - off] : 0;
        __syncthreads();
        scan[tid] += v;
        __syncthreads();
    }
    int start = scan[tid] - c;
    for (int k = 0; k < c; k++) {
        int pos = start + k;
        if (pos < MAXN) g_mem[cls * MAXN + pos] = loc[k];
    }
    if (tid == 255) g_n[cls] = scan[255] < MAXN ? scan[255] : MAXN;
}

// ---------------- kernel 1: per (layer,class) full-class cosine blocks -------------
__global__ __launch_bounds__(256) void sims_kernel(const float* __restrict__ feats) {
    extern __shared__ float4 stage[];            // SCAP rows, DPAD float4 stride
    __shared__ int           midx[MAXN];
    __shared__ float         sinv[MAXN];
    __shared__ const float4* rowp[MAXN];

    const int cls = blockIdx.x & (NCLS - 1);
    const int l   = blockIdx.x >> 7;
    const int tid = threadIdx.x;
    const int n   = g_n[cls];
    if (n == 0) return;

    for (int r = tid; r < n; r += 256) midx[r] = g_mem[cls * MAXN + r];
    __syncthreads();

    // ---- stage rows via cp.async (high MLP, no register round-trip) ----
    const float* F = feats + (size_t)l * NS * D;
    const int nst = n < SCAP ? n : SCAP;
    {
        uint32_t sbase = (uint32_t)__cvta_generic_to_shared(stage);
        for (int q = tid; q < nst * D4; q += 256) {
            int r = q >> 7, cc = q & 127;
            cp_async16(sbase + (uint32_t)(r * DPAD + cc) * 16u,
                       (const float4*)(F + (size_t)midx[r] * D) + cc);
        }
        asm volatile("cp.async.commit_group;\ncp.async.wait_group 0;\n" ::: "memory");
    }
    for (int r = tid; r < n; r += 256)
        rowp[r] = (r < nst) ? (const float4*)(stage + r * DPAD)
                            : (const float4*)(F + (size_t)midx[r] * D);
    __syncthreads();

    // ---- inverse norms (warp per row; same reduction tree as reference path) ----
    {
        const int w = tid >> 5, lane = tid & 31;
        for (int r = w; r < n; r += 8) {
            const float4* a = rowp[r];
            float ss = 0.f;
#pragma unroll
            for (int k = 0; k < 4; k++) {
                float4 v = a[lane + 32 * k];
                ss += v.x * v.x + v.y * v.y + v.z * v.z + v.w * v.w;
            }
#pragma unroll
            for (int o = 16; o; o >>= 1) ss += __shfl_xor_sync(0xffffffffu, ss, o);
            if (lane == 0) sinv[r] = 1.0f / fmaxf(sqrtf(ss), 1e-8f);
        }
    }
    __syncthreads();

    // ---- sims: 4 pairs per warp (8 lanes per dot), write straight to global ----
    float* gsim = g_sim + (size_t)(l * NCLS + cls) * MAXN * MAXN;
    {
        const int w = tid >> 5, lane = tid & 31;
        const int grp = lane >> 3, l8 = lane & 7;
        const int npair = n * (n - 1) / 2;
        for (int pb = w * 4; pb < npair; pb += 32) {
            int p  = pb + grp;
            int pc = (p < npair) ? p : npair - 1;
            int i = (int)((1.0f + sqrtf(8.0f * (float)pc + 1.0f)) * 0.5f);
            while (i * (i - 1) / 2 > pc) i--;
            while ((i + 1) * i / 2 <= pc) i++;
            int j = pc - i * (i - 1) / 2;
            const float4* a = rowp[i];
            const float4* b = rowp[j];
            float dot = 0.f;
#pragma unroll
            for (int k = 0; k < 16; k++) {
                float4 x = a[l8 + 8 * k];
                float4 y = b[l8 + 8 * k];
                dot += x.x * y.x + x.y * y.y + x.z * y.z + x.w * y.w;
            }
#pragma unroll
            for (int o = 4; o; o >>= 1) dot += __shfl_xor_sync(0xffffffffu, dot, o);
            if (l8 == 0 && p < npair) {
                float s = dot * sinv[i] * sinv[j];
                s = fminf(fmaxf(s, -1.0f), 1.0f);   // fp32 clip bounds round to +/-1
                gsim[i * MAXN + j] = s;
                gsim[j * MAXN + i] = s;
            }
        }
        // diag = clip(~1, 1-1e-8) -> exactly 1.0f in fp32
        for (int i = tid; i < n; i += 256) gsim[i * MAXN + i] = 1.0f;
    }
}

// top-5 with jax.lax.top_k tie-break (equal values -> lower index)
__device__ __forceinline__ void top5_row(const float* row, int n, int self, int* ch) {
#pragma unroll
    for (int t = 0; t < KTOP; t++) {
        float bv = 0.f;   // only strictly-positive sims are candidates
        int   bj = -1;
        for (int j = 0; j < n; j++) {
            if (j == self) continue;
            bool used = false;
            for (int u = 0; u < t; u++) if (ch[u] == j) used = true;
            if (used) continue;
            float v = row[j];
            if (v > bv) { bv = v; bj = j; }
        }
        ch[t] = bj;
    }
}

// knn mask + ema on an n2 x n2 sim block; writes compacted masked-A, sym-mask, ema
__device__ __forceinline__ void knn_store(const float* sim, int n2, int l, int cls,
                                          unsigned char* msk, unsigned char* keep) {
    const int tid = threadIdx.x;
    for (int p = tid; p < n2 * MAXN; p += blockDim.x) msk[p] = 0;
    __syncthreads();
    float emaval = 0.f;
    if (tid < n2) {
        const float* row = sim + tid * MAXN;
        float rs = 0.f;
        int dg = 0, cand = 0;
        for (int j = 0; j < n2; j++) {
            float v = row[j];
            if (v > 0.f) { rs += v; dg++; if (j != tid) cand++; }
        }
        float degf = (float)(dg > 0 ? dg : 1);
        float sc   = 1.0f / (1.0f + expf(-rs / degf));
        emaval    = 0.45f + 0.1f * sc;           // MOM*0.5 + (1-MOM)*score
        keep[tid] = (cand >= KTOP) ? 1 : 0;
    }
    __syncthreads();
    if (tid < n2 && keep[tid]) {
        const float* row = sim + tid * MAXN;
        int ch[KTOP];
        top5_row(row, n2, tid, ch);
#pragma unroll
        for (int t = 0; t < KTOP; t++) {
            int j = ch[t];
            if (j >= 0 && keep[j]) msk[tid * MAXN + j] = 1;
        }
    }
    __syncthreads();
    float*         gA = g_A   + (size_t)(l * NCLS + cls) * MAXN * MAXN;
    unsigned char* gm = g_msk + (size_t)(l * NCLS + cls) * MAXN * MAXN;
    for (int p = tid; p < n2 * MAXN; p += blockDim.x) {
        int i = p >> 6, j = p & 63;
        unsigned char sym = (unsigned char)(msk[p] | ((j < n2) ? msk[j * MAXN + i] : 0));
        gm[p] = sym;
        gA[p] = sym ? sim[p] : 0.f;              // A = sim * M (masked sims > 0)
    }
    if (tid < n2) g_ema[(l * NCLS + cls) * MAXN + tid] = emaval;
}

// ---------------- kernel 2: subset selection + layer-7 compacted outputs -----------
__global__ __launch_bounds__(256) void subset_kernel() {
    __shared__ float         sim[MAXN * MAXN];
    __shared__ float         sim2[MAXN * MAXN];
    __shared__ unsigned char msk[MAXN * MAXN];
    __shared__ unsigned char keep[MAXN], insub[MAXN];
    __shared__ int           smap[MAXN];
    __shared__ int           sn2;

    const int cls = blockIdx.x, tid = threadIdx.x;
    const int n = g_n[cls];
    if (n == 0) { if (tid == 0) g_n2[cls] = 0; return; }

    const float* gsim = g_sim + (size_t)((LYR - 1) * NCLS + cls) * MAXN * MAXN;
    for (int p = tid; p < n * MAXN; p += 256) sim[p] = gsim[p];
    __syncthreads();

    if (tid < n) {
        insub[tid] = 0;
        const float* row = sim + tid * MAXN;
        int cand = 0;
        for (int j = 0; j < n; j++)
            if (j != tid && row[j] > 0.f) cand++;
        keep[tid] = (cand >= KTOP) ? 1 : 0;
    }
    __syncthreads();
    if (tid < n && keep[tid]) {
        const float* row = sim + tid * MAXN;
        int ch[KTOP];
        top5_row(row, n, tid, ch);
#pragma unroll
        for (int t = 0; t < KTOP; t++) {
            int j = ch[t];
            if (j >= 0 && keep[j]) { insub[tid] = 1; insub[j] = 1; }  // benign race
        }
    }
    __syncthreads();
    if (tid == 0) {
        int m = 0;
        for (int i = 0; i < n; i++)
            if (insub[i]) { smap[m] = i; g_smap[cls * MAXN + m] = i; m++; }
        sn2 = m;
        g_n2[cls] = m;
    }
    __syncthreads();
    const int n2 = sn2;
    if (n2 == 0) return;

    // layer-7 compacted outputs straight from the in-smem full-class block
    for (int p = tid; p < n2 * n2; p += 256) {
        int i = p / n2, j = p % n2;
        sim2[i * MAXN + j] = sim[smap[i] * MAXN + smap[j]];
    }
    __syncthreads();
    knn_store(sim2, n2, LYR - 1, cls, msk, keep);
}

// ---------------- kernel 3: per (class, layer 0..6) subset knn from stored sims ----
__global__ __launch_bounds__(256) void knn_kernel() {
    __shared__ int           smap[MAXN];
    __shared__ float         sim[MAXN * MAXN];
    __shared__ unsigned char msk[MAXN * MAXN];
    __shared__ unsigned char keep[MAXN];

    const int cls = blockIdx.x & (NCLS - 1);
    const int l   = blockIdx.x >> 7;        // 0..6
    const int tid = threadIdx.x;
    const int n2  = g_n2[cls];
    if (n2 == 0) return;

    for (int r = tid; r < n2; r += 256) smap[r] = g_smap[cls * MAXN + r];
    __syncthreads();
    const float* gsim = g_sim + (size_t)(l * NCLS + cls) * MAXN * MAXN;
    for (int p = tid; p < n2 * n2; p += 256) {
        int i = p / n2, j = p % n2;
        sim[i * MAXN + j] = gsim[smap[i] * MAXN + smap[j]];
    }
    __syncthreads();
    knn_store(sim, n2, l, cls, msk, keep);
}

// ---------------- kernel 4: streaming accumulation + fused final combine -----------
__global__ __launch_bounds__(128) void accum_final(float* __restrict__ out) {
    __shared__ float wsh[MAXN];
    __shared__ float swn[4], swd[4];
    __shared__ int   done;

    const int blk = blockIdx.x;              // 0..895
    const int cls = blk & (NCLS - 1);
    const int t   = blk >> 7;                // 0..6
    const int tid = threadIdx.x;
    const int n2  = g_n2[cls];

    float pnum = 0.f, pden = 0.f;
    if (n2 > 1) {
        for (int r = tid; r < n2; r += 128)
            wsh[r] = g_ema[(t * NCLS + cls) * MAXN + r];
        __syncthreads();
        const size_t bp = (size_t)(t * NCLS + cls) * MAXN * MAXN;
        const size_t bc = (size_t)((t + 1) * NCLS + cls) * MAXN * MAXN;
        // contiguous streaming; zero masks on diagonal & tail auto-skip
        for (int p = tid; p < n2 * MAXN; p += 128) {
            int ml = g_msk[bp + p];
            int mc = g_msk[bc + p];
            if (ml | mc) {
                int i = p >> 6, j = p & 63;
                float w  = wsh[i] * wsh[j];
                float d  = g_A[bc + p] - g_A[bp + p];
                pnum += d * d * w;
                pden += w;
            }
        }
    }
#pragma unroll
    for (int o = 16; o; o >>= 1) {
        pnum += __shfl_xor_sync(0xffffffffu, pnum, o);
        pden += __shfl_xor_sync(0xffffffffu, pden, o);
    }
    if ((tid & 31) == 0) { swn[tid >> 5] = pnum; swd[tid >> 5] = pden; }
    __syncthreads();
    if (tid == 0) {
        g_pnum[blk] = swn[0] + swn[1] + swn[2] + swn[3];
        g_pden[blk] = swd[0] + swd[1] + swd[2] + swd[3];
        __threadfence();
        int old = atomicAdd(&g_ctr, 1);
        done = (old == NT * NCLS - 1) ? 1 : 0;
    }
    __syncthreads();
    if (!done) return;

    // last block: deterministic combine of all 896 partials
    __shared__ float red[128];
    __shared__ float tnum[NT], tden[NT];
    for (int t2 = 0; t2 < NT; t2++) {
        red[tid] = g_pnum[t2 * NCLS + tid];
        __syncthreads();
        for (int s = 64; s; s >>= 1) { if (tid < s) red[tid] += red[tid + s]; __syncthreads(); }
        if (tid == 0) tnum[t2] = red[0];
        __syncthreads();
        red[tid] = g_pden[t2 * NCLS + tid];
        __syncthreads();
        for (int s = 64; s; s >>= 1) { if (tid < s) red[tid] += red[tid + s]; __syncthreads(); }
        if (tid == 0) tden[t2] = red[0];
        __syncthreads();
    }
    if (tid == 0) {
        float raw = 0.f;
        for (int t2 = 0; t2 < NT; t2++)
            if (tden[t2] > 0.f)                       // M_eff.sum() > 0 <=> any edge
                raw += tnum[t2] / fmaxf(tden[t2], 1e-8f);
        out[0] = 16.0f * (raw / 7.0f);                // LAMBDA_ALIGN_K * raw / (L-1)
        g_ctr = 0;                                    // reset for next graph replay
    }
}

extern "C" void kernel_launch(void* const* d_in, const int* in_sizes, int n_in,
                              void* d_out, int out_size) {
    const float* feats  = (const float*)d_in[0];
    const int*   labels = (const int*)d_in[1];   // int32 or int64; detected at runtime
    const int*   sids   = (const int*)d_in[2];
    float*       out    = (float*)d_out;

    const int DYN = SCAP * DPAD * 16;            // 41.3 KB padded stage
    cudaFuncSetAttribute(sims_kernel, cudaFuncAttributeMaxDynamicSharedMemorySize, DYN);

    members_kernel<<<NCLS, 256>>>(labels, sids);
    sims_kernel<<<LYR * NCLS, 256, DYN>>>(feats);
    subset_kernel<<<NCLS, 256>>>();
    knn_kernel<<<NT * NCLS, 256>>>();
    accum_final<<<NT * NCLS, 128>>>(out);
}

// round 11
// speedup vs baseline: 1.3905x; 1.1805x over previous
#include <cuda_runtime.h>
#include <math.h>
#include <stdint.h>

#define NS    2048
#define D     512
#define D4    128
#define DPAD  129          // padded float4 row stride in stage (kills bank conflicts)
#define LYR   8
#define NT    7            // layer pairs
#define NCLS  128
#define MAXN  64
#define MAXNP 65           // padded smem sim/mask row stride (kills 32-way conflicts)
#define SCAP  20           // staged rows: 20*129*16B = 41.3KB -> 5 CTAs/SM
#define KTOP  5

// ---------------- device scratch (no allocations allowed) ----------------
__device__ int           g_mem[NCLS * MAXN];     // full-class member lists
__device__ int           g_n[NCLS];
__device__ int           g_smap[NCLS * MAXN];    // subset member-position map
__device__ int           g_n2[NCLS];
__device__ float         g_sim[(size_t)LYR * NCLS * MAXN * MAXN];   // full-class sims
__device__ float         g_A[(size_t)LYR * NCLS * MAXN * MAXN];     // masked symmetric A
__device__ unsigned char g_msk[(size_t)LYR * NCLS * MAXN * MAXN];   // symmetric masks
__device__ float         g_ema[LYR * NCLS * MAXN];
__device__ float         g_pnum[NT * NCLS];
__device__ float         g_pden[NT * NCLS];
__device__ int           g_ctr = 0;

__device__ __forceinline__ void cp_async16(uint32_t smem_addr, const void* gptr) {
    asm volatile("cp.async.cg.shared.global [%0], [%1], 16;\n"
                 :: "r"(smem_addr), "l"(gptr) : "memory");
}

// ---------------- kernel 0: member lists (hoisted out of the heavy kernel) ---------
__global__ __launch_bounds__(256) void members_kernel(const int* __restrict__ labels,
                                                      const int* __restrict__ sids32) {
    __shared__ int scan[256];
    const int cls = blockIdx.x, tid = threadIdx.x;
    // sample_ids = arange. int64 -> int32 words [0,0,1,0,...]; word[2]==1 iff int64
    const int is64 = (sids32[2] == 1) ? 1 : 0;

    int loc[8]; int c = 0;
#pragma unroll
    for (int k = 0; k < 8; k++) {
        int gi = tid * 8 + k;
        int lb = is64 ? labels[2 * gi] : labels[gi];
        if (lb == cls) loc[c++] = gi;
    }
    scan[tid] = c;
    __syncthreads();
    for (int off = 1; off < 256; off <<= 1) {
        int v = (tid >= off) ? scan[tid - off] : 0;
        __syncthreads();
        scan[tid] += v;
        __syncthreads();
    }
    int start = scan[tid] - c;
    for (int k = 0; k < c; k++) {
        int pos = start + k;
        if (pos < MAXN) g_mem[cls * MAXN + pos] = loc[k];
    }
    if (tid == 255) g_n[cls] = scan[255] < MAXN ? scan[255] : MAXN;
}

// ---------------- kernel 1: per (layer,class) full-class cosine blocks -------------
// Warp-per-row: row i lives in 16 registers/lane; only row j streams from LDS.
// Halves shared-memory traffic vs the pair-per-group scheme.
__global__ __launch_bounds__(256) void sims_kernel(const float* __restrict__ feats) {
    extern __shared__ float4 stage[];            // SCAP rows, DPAD float4 stride
    __shared__ int           midx[MAXN];
    __shared__ float         sinv[MAXN];
    __shared__ const float4* rowp[MAXN];

    const int cls = blockIdx.x & (NCLS - 1);
    const int l   = blockIdx.x >> 7;
    const int tid = threadIdx.x;
    const int n   = g_n[cls];
    if (n == 0) return;

    for (int r = tid; r < n; r += 256) midx[r] = g_mem[cls * MAXN + r];
    __syncthreads();

    // ---- stage rows via cp.async; rows beyond SCAP fall back to global (L1) ----
    const float* F = feats + (size_t)l * NS * D;
    const int nst = n < SCAP ? n : SCAP;
    {
        uint32_t sbase = (uint32_t)__cvta_generic_to_shared(stage);
        for (int q = tid; q < nst * D4; q += 256) {
            int r = q >> 7, cc = q & 127;
            cp_async16(sbase + (uint32_t)(r * DPAD + cc) * 16u,
                       (const float4*)(F + (size_t)midx[r] * D) + cc);
        }
        asm volatile("cp.async.commit_group;\ncp.async.wait_group 0;\n" ::: "memory");
    }
    for (int r = tid; r < n; r += 256)
        rowp[r] = (r < nst) ? (const float4*)(stage + r * DPAD)
                            : (const float4*)(F + (size_t)midx[r] * D);
    __syncthreads();

    const int w = tid >> 5, lane = tid & 31;

    // ---- inverse norms (warp per row; same reduction tree as reference path) ----
    for (int r = w; r < n; r += 8) {
        const float4* a = rowp[r];
        float ss = 0.f;
#pragma unroll
        for (int k = 0; k < 4; k++) {
            float4 v = a[lane + 32 * k];
            ss += v.x * v.x + v.y * v.y + v.z * v.z + v.w * v.w;
        }
#pragma unroll
        for (int o = 16; o; o >>= 1) ss += __shfl_xor_sync(0xffffffffu, ss, o);
        if (lane == 0) sinv[r] = 1.0f / fmaxf(sqrtf(ss), 1e-8f);
    }
    __syncthreads();

    // ---- sims: warp-per-row-i; i-row in registers, j-rows streamed from LDS ----
    float* gsim = g_sim + (size_t)(l * NCLS + cls) * MAXN * MAXN;
    for (int i = w; i < n; i += 8) {
        const float4* a = rowp[i];
        float4 ar[4];
#pragma unroll
        for (int k = 0; k < 4; k++) ar[k] = a[lane + 32 * k];
        const float si = sinv[i];
        for (int j = 0; j < i; j++) {
            const float4* b = rowp[j];
            float dot = 0.f;
#pragma unroll
            for (int k = 0; k < 4; k++) {
                float4 y = b[lane + 32 * k];
                dot += ar[k].x * y.x + ar[k].y * y.y + ar[k].z * y.z + ar[k].w * y.w;
            }
#pragma unroll
            for (int o = 16; o; o >>= 1) dot += __shfl_xor_sync(0xffffffffu, dot, o);
            if (lane == 0) {
                float s = dot * si * sinv[j];
                s = fminf(fmaxf(s, -1.0f), 1.0f);   // fp32 clip bounds round to +/-1
                gsim[i * MAXN + j] = s;
                gsim[j * MAXN + i] = s;
            }
        }
    }
    // diag = clip(~1, 1-1e-8) -> exactly 1.0f in fp32
    for (int i = tid; i < n; i += 256) gsim[i * MAXN + i] = 1.0f;
}

// top-5 with jax.lax.top_k tie-break (equal values -> lower index)
__device__ __forceinline__ void top5_row(const float* row, int n, int self, int* ch) {
#pragma unroll
    for (int t = 0; t < KTOP; t++) {
        float bv = 0.f;   // only strictly-positive sims are candidates
        int   bj = -1;
        for (int j = 0; j < n; j++) {
            if (j == self) continue;
            bool used = false;
            for (int u = 0; u < t; u++) if (ch[u] == j) used = true;
            if (used) continue;
            float v = row[j];
            if (v > bv) { bv = v; bj = j; }
        }
        ch[t] = bj;
    }
}

// knn mask + ema on an n2 x n2 sim block (MAXNP stride); writes compacted outputs
__device__ __forceinline__ void knn_store(const float* sim, int n2, int l, int cls,
                                          unsigned char* msk, unsigned char* keep) {
    const int tid = threadIdx.x;
    const int w = tid >> 5, lane = tid & 31;
    for (int i = w; i < n2; i += 8)
        for (int j = lane; j < MAXNP; j += 32) msk[i * MAXNP + j] = 0;
    __syncthreads();
    float emaval = 0.f;
    if (tid < n2) {
        const float* row = sim + tid * MAXNP;
        float rs = 0.f;
        int dg = 0, cand = 0;
        for (int j = 0; j < n2; j++) {
            float v = row[j];
            if (v > 0.f) { rs += v; dg++; if (j != tid) cand++; }
        }
        float degf = (float)(dg > 0 ? dg : 1);
        float sc   = 1.0f / (1.0f + expf(-rs / degf));
        emaval    = 0.45f + 0.1f * sc;           // MOM*0.5 + (1-MOM)*score
        keep[tid] = (cand >= KTOP) ? 1 : 0;
    }
    __syncthreads();
    if (tid < n2 && keep[tid]) {
        const float* row = sim + tid * MAXNP;
        int ch[KTOP];
        top5_row(row, n2, tid, ch);
#pragma unroll
        for (int t = 0; t < KTOP; t++) {
            int j = ch[t];
            if (j >= 0 && keep[j]) msk[tid * MAXNP + j] = 1;
        }
    }
    __syncthreads();
    float*         gA = g_A   + (size_t)(l * NCLS + cls) * MAXN * MAXN;
    unsigned char* gm = g_msk + (size_t)(l * NCLS + cls) * MAXN * MAXN;
    for (int i = w; i < n2; i += 8)
        for (int j = lane; j < MAXN; j += 32) {
            unsigned char sym = 0; float av = 0.f;
            if (j < n2) {
                sym = (unsigned char)(msk[i * MAXNP + j] | msk[j * MAXNP + i]);
                av  = sym ? sim[i * MAXNP + j] : 0.f;   // A = sim * M
            }
            gm[i * MAXN + j] = sym;
            gA[i * MAXN + j] = av;
        }
    if (tid < n2) g_ema[(l * NCLS + cls) * MAXN + tid] = emaval;
}

// ---------------- kernel 2: subset selection + layer-7 compacted outputs -----------
__global__ __launch_bounds__(256) void subset_kernel() {
    __shared__ float         sim[MAXN * MAXNP];
    __shared__ float         sim2[MAXN * MAXNP];
    __shared__ unsigned char msk[MAXN * MAXNP];
    __shared__ unsigned char keep[MAXN], insub[MAXN];
    __shared__ int           smap[MAXN];
    __shared__ int           sn2;

    const int cls = blockIdx.x, tid = threadIdx.x;
    const int w = tid >> 5, lane = tid & 31;
    const int n = g_n[cls];
    if (n == 0) { if (tid == 0) g_n2[cls] = 0; return; }

    const float* gsim = g_sim + (size_t)((LYR - 1) * NCLS + cls) * MAXN * MAXN;
    for (int i = w; i < n; i += 8)
        for (int j = lane; j < n; j += 32)
            sim[i * MAXNP + j] = gsim[i * MAXN + j];
    __syncthreads();

    if (tid < n) {
        insub[tid] = 0;
        const float* row = sim + tid * MAXNP;
        int cand = 0;
        for (int j = 0; j < n; j++)
            if (j != tid && row[j] > 0.f) cand++;
        keep[tid] = (cand >= KTOP) ? 1 : 0;
    }
    __syncthreads();
    if (tid < n && keep[tid]) {
        const float* row = sim + tid * MAXNP;
        int ch[KTOP];
        top5_row(row, n, tid, ch);
#pragma unroll
        for (int t = 0; t < KTOP; t++) {
            int j = ch[t];
            if (j >= 0 && keep[j]) { insub[tid] = 1; insub[j] = 1; }  // benign race
        }
    }
    __syncthreads();
    if (tid == 0) {
        int m = 0;
        for (int i = 0; i < n; i++)
            if (insub[i]) { smap[m] = i; g_smap[cls * MAXN + m] = i; m++; }
        sn2 = m;
        g_n2[cls] = m;
    }
    __syncthreads();
    const int n2 = sn2;
    if (n2 == 0) return;

    // layer-7 compacted outputs straight from the in-smem full-class block
    for (int i = w; i < n2; i += 8)
        for (int j = lane; j < n2; j += 32)
            sim2[i * MAXNP + j] = sim[smap[i] * MAXNP + smap[j]];
    __syncthreads();
    knn_store(sim2, n2, LYR - 1, cls, msk, keep);
}

// ---------------- kernel 3: per (class, layer 0..6) subset knn from stored sims ----
__global__ __launch_bounds__(256) void knn_kernel() {
    __shared__ int           smap[MAXN];
    __shared__ float         sim[MAXN * MAXNP];
    __shared__ unsigned char msk[MAXN * MAXNP];
    __shared__ unsigned char keep[MAXN];

    const int cls = blockIdx.x & (NCLS - 1);
    const int l   = blockIdx.x >> 7;        // 0..6
    const int tid = threadIdx.x;
    const int w = tid >> 5, lane = tid & 31;
    const int n2  = g_n2[cls];
    if (n2 == 0) return;

    for (int r = tid; r < n2; r += 256) smap[r] = g_smap[cls * MAXN + r];
    __syncthreads();
    const float* gsim = g_sim + (size_t)(l * NCLS + cls) * MAXN * MAXN;
    for (int i = w; i < n2; i += 8)
        for (int j = lane; j < n2; j += 32)
            sim[i * MAXNP + j] = gsim[smap[i] * MAXN + smap[j]];
    __syncthreads();
    knn_store(sim, n2, l, cls, msk, keep);
}

// ---------------- kernel 4: streaming accumulation + fused final combine -----------
__global__ __launch_bounds__(128) void accum_final(float* __restrict__ out) {
    __shared__ float wsh[MAXN];
    __shared__ float swn[4], swd[4];
    __shared__ int   done;

    const int blk = blockIdx.x;              // 0..895
    const int cls = blk & (NCLS - 1);
    const int t   = blk >> 7;                // 0..6
    const int tid = threadIdx.x;
    const int n2  = g_n2[cls];

    float pnum = 0.f, pden = 0.f;
    if (n2 > 1) {
        for (int r = tid; r < n2; r += 128)
            wsh[r] = g_ema[(t * NCLS + cls) * MAXN + r];
        __syncthreads();
        const size_t bp = (size_t)(t * NCLS + cls) * MAXN * MAXN;
        const size_t bc = (size_t)((t + 1) * NCLS + cls) * MAXN * MAXN;
        // contiguous streaming; zero masks on diagonal & tail auto-skip
        for (int p = tid; p < n2 * MAXN; p += 128) {
            int ml = g_msk[bp + p];
            int mc = g_msk[bc + p];
            if (ml | mc) {
                int i = p >> 6, j = p & 63;
                float w  = wsh[i] * wsh[j];
                float d  = g_A[bc + p] - g_A[bp + p];
                pnum += d * d * w;
                pden += w;
            }
        }
    }
#pragma unroll
    for (int o = 16; o; o >>= 1) {
        pnum += __shfl_xor_sync(0xffffffffu, pnum, o);
        pden += __shfl_xor_sync(0xffffffffu, pden, o);
    }
    if ((tid & 31) == 0) { swn[tid >> 5] = pnum; swd[tid >> 5] = pden; }
    __syncthreads();
    if (tid == 0) {
        g_pnum[blk] = swn[0] + swn[1] + swn[2] + swn[3];
        g_pden[blk] = swd[0] + swd[1] + swd[2] + swd[3];
        __threadfence();
        int old = atomicAdd(&g_ctr, 1);
        done = (old == NT * NCLS - 1) ? 1 : 0;
    }
    __syncthreads();
    if (!done) return;

    // last block: deterministic combine of all 896 partials
    __shared__ float red[128];
    __shared__ float tnum[NT], tden[NT];
    for (int t2 = 0; t2 < NT; t2++) {
        red[tid] = g_pnum[t2 * NCLS + tid];
        __syncthreads();
        for (int s = 64; s; s >>= 1) { if (tid < s) red[tid] += red[tid + s]; __syncthreads(); }
        if (tid == 0) tnum[t2] = red[0];
        __syncthreads();
        red[tid] = g_pden[t2 * NCLS + tid];
        __syncthreads();
        for (int s = 64; s; s >>= 1) { if (tid < s) red[tid] += red[tid + s]; __syncthreads(); }
        if (tid == 0) tden[t2] = red[0];
        __syncthreads();
    }
    if (tid == 0) {
        float raw = 0.f;
        for (int t2 = 0; t2 < NT; t2++)
            if (tden[t2] > 0.f)                       // M_eff.sum() > 0 <=> any edge
                raw += tnum[t2] / fmaxf(tden[t2], 1e-8f);
        out[0] = 16.0f * (raw / 7.0f);                // LAMBDA_ALIGN_K * raw / (L-1)
        g_ctr = 0;                                    // reset for next graph replay
    }
}

extern "C" void kernel_launch(void* const* d_in, const int* in_sizes, int n_in,
                              void* d_out, int out_size) {
    const float* feats  = (const float*)d_in[0];
    const int*   labels = (const int*)d_in[1];   // int32 or int64; detected at runtime
    const int*   sids   = (const int*)d_in[2];
    float*       out    = (float*)d_out;

    const int DYN = SCAP * DPAD * 16;            // 41.3 KB padded stage
    cudaFuncSetAttribute(sims_kernel, cudaFuncAttributeMaxDynamicSharedMemorySize, DYN);

    members_kernel<<<NCLS, 256>>>(labels, sids);
    sims_kernel<<<LYR * NCLS, 256, DYN>>>(feats);
    subset_kernel<<<NCLS, 256>>>();
    knn_kernel<<<NT * NCLS, 256>>>();
    accum_final<<<NT * NCLS, 128>>>(out);
}